// round 2
// baseline (speedup 1.0000x reference)
#include <cuda_runtime.h>
#include <math_constants.h>

// Problem constants (from reference setup_inputs)
#define N_DEC 16     // N
#define M_LEN 128    // M
#define V_VOC 64     // V
#define H_DIM 128    // H
#define K_TPL 8      // K
#define NP1 17       // N+1
#define ROWS 136     // K*(N+1)

// One block per batch element b. 256 threads.
// Phase 1: compute sel[k] = argmax_n (w_sem[t-9,k*17+n]·emb + b_sem + gumbel) over n<=span
// Phase 2: for each k with sel>0: scan decodings[b,sel-1] for effective length
//          (cached in smem), then pack-copy prefix into output; zero tail.
__global__ __launch_bounds__(256, 4)
void fused_template_pack_kernel(
    const float* __restrict__ decodings,   // [B,16,128,64]
    const float* __restrict__ type_emb,    // [24,128]
    const float* __restrict__ w_sem,       // [15,136,128]
    const float* __restrict__ b_sem,       // [15,136]
    const float* __restrict__ gumbel,      // [B,8,17]
    const int*   __restrict__ target_types,// [B]
    const int*   __restrict__ spans,       // [B]
    float*       __restrict__ out)         // [B,128,64]
{
    const int b    = blockIdx.x;
    const int tid  = threadIdx.x;
    const int lane = tid & 31;
    const int warp = tid >> 5;

    __shared__ float  s_emb[H_DIM];
    __shared__ int    s_sel[K_TPL];
    __shared__ int    s_len;
    __shared__ float4 s_row[M_LEN * V_VOC / 4];   // 32 KB: one template row

    const int t = target_types[b];

    // ---------------- Phase 1: template selection ----------------
    if (t == 20) {
        // special start template: row 0 -> child 1, rows 1..7 -> pad (0)
        if (tid < K_TPL) s_sel[tid] = (tid == 0) ? 1 : 0;
    } else {
        if (tid < H_DIM) s_emb[tid] = type_emb[t * H_DIM + tid];
        __syncthreads();

        const int ti = t - 9;
        const float* __restrict__ w  = w_sem + (size_t)ti * ROWS * H_DIM;
        const float* __restrict__ bb = b_sem + (size_t)ti * ROWS;
        const int span = spans[b];
        const int k = warp;            // 8 warps, one per template row

        float best = -CUDART_INF_F;
        int   bestn = 0;
        #pragma unroll 1
        for (int n = 0; n < NP1; n++) {
            const int r = k * NP1 + n;
            const float* __restrict__ wr = w + (size_t)r * H_DIM;
            float acc = wr[lane]      * s_emb[lane]
                      + wr[lane + 32] * s_emb[lane + 32]
                      + wr[lane + 64] * s_emb[lane + 64]
                      + wr[lane + 96] * s_emb[lane + 96];
            #pragma unroll
            for (int o = 16; o; o >>= 1)
                acc += __shfl_xor_sync(0xffffffffu, acc, o);
            if (lane == 0 && n <= span) {
                float val = acc + bb[r] + gumbel[((size_t)b * K_TPL + k) * NP1 + n];
                if (val > best) { best = val; bestn = n; }   // first-max tiebreak
            }
        }
        if (lane == 0) s_sel[k] = bestn;
    }
    __syncthreads();

    // ---------------- Phase 2: length scan + packed copy ----------------
    const float* __restrict__ dec = decodings + (size_t)b * N_DEC * M_LEN * V_VOC;
    float* __restrict__ outb = out + (size_t)b * M_LEN * V_VOC;

    const int v4    = tid & 15;        // 16 float4 (=64 floats) per position m
    const int mbase = tid >> 4;        // 16 positions per iteration

    int cur = 0;
    #pragma unroll 1
    for (int k = 0; k < K_TPL; k++) {
        const int sel = s_sel[k];      // uniform across block
        if (sel == 0) continue;        // pad template: length 0

        const float4* __restrict__ row4 =
            (const float4*)(dec + (size_t)(sel - 1) * (M_LEN * V_VOC));

        if (tid == 0) s_len = 0;
        __syncthreads();

        #pragma unroll 1
        for (int iter = 0; iter < 8; iter++) {
            const int m = iter * 16 + mbase;
            float4 x = row4[m * 16 + v4];
            s_row[m * 16 + v4] = x;
            // d[m,0] lives in .x of the v4==0 thread of this 16-lane group
            float d0 = __shfl_sync(0xffffffffu, x.x, lane & 16, 32);
            float cm;
            if (v4 == 0) cm = fmaxf(fmaxf(x.y, x.z), x.w);        // exclude v=0
            else         cm = fmaxf(fmaxf(x.x, x.y), fmaxf(x.z, x.w));
            #pragma unroll
            for (int o = 8; o; o >>= 1)
                cm = fmaxf(cm, __shfl_xor_sync(0xffffffffu, cm, o));
            // argmax != 0  <=>  max over v>0 strictly beats d[m,0]
            if (v4 == 0 && cm > d0) atomicMax(&s_len, m + 1);
        }
        __syncthreads();

        const int len = s_len;
        const int eff = min(len, M_LEN - cur);
        const float* __restrict__ srow = (const float*)s_row;
        float* __restrict__ dst = outb + cur * V_VOC;
        const int total = eff * V_VOC;
        for (int i = tid; i < total; i += 256) dst[i] = srow[i];
        cur += eff;
        __syncthreads();   // s_row / s_len reused next k
    }

    // zero the unpacked tail (output buffer is poisoned by the harness)
    for (int i = cur * V_VOC + tid; i < M_LEN * V_VOC; i += 256)
        outb[i] = 0.0f;
}

extern "C" void kernel_launch(void* const* d_in, const int* in_sizes, int n_in,
                              void* d_out, int out_size)
{
    const float* decodings    = (const float*)d_in[0];
    const float* type_emb     = (const float*)d_in[1];
    const float* w_sem        = (const float*)d_in[2];
    const float* b_sem        = (const float*)d_in[3];
    const float* gumbel       = (const float*)d_in[4];
    const int*   target_types = (const int*)  d_in[5];
    const int*   spans        = (const int*)  d_in[6];
    float*       out          = (float*)d_out;

    const int B = in_sizes[5];   // target_types element count

    fused_template_pack_kernel<<<B, 256>>>(
        decodings, type_emb, w_sem, b_sem, gumbel, target_types, spans, out);
}

// round 4
// speedup vs baseline: 1.4286x; 1.4286x over previous
#include <cuda_runtime.h>
#include <math_constants.h>

#define N_DEC 16
#define M_LEN 128
#define V_VOC 64
#define H_DIM 128
#define K_TPL 8
#define NP1 17
#define ROWS 136
#define MAXB 4096

// scratch between the two kernels
__device__ int g_src[MAXB * K_TPL];   // absolute decodings row index (b*16 + sel-1), or -1 if pad
__device__ int g_eff[MAXB * K_TPL];   // effective copied length
__device__ int g_off[MAXB * K_TPL];   // destination offset (positions)
__device__ int g_tot[MAXB];           // total packed length

// ---------------- Kernel 1: selection + per-row length scan + offsets ----------------
__global__ __launch_bounds__(256, 8)
void select_len_kernel(
    const float* __restrict__ decodings,   // [B,16,128,64]
    const float* __restrict__ type_emb,    // [24,128]
    const float* __restrict__ w_sem,       // [15,136,128]
    const float* __restrict__ b_sem,       // [15,136]
    const float* __restrict__ gumbel,      // [B,8,17]
    const int*   __restrict__ target_types,// [B]
    const int*   __restrict__ spans)       // [B]
{
    const int b    = blockIdx.x;
    const int tid  = threadIdx.x;
    const int lane = tid & 31;
    const int k    = tid >> 5;             // warp = template row, 8 warps

    __shared__ float s_emb[H_DIM];
    __shared__ int   s_sel[K_TPL];
    __shared__ int   s_len[K_TPL];

    const int t = target_types[b];

    // ---- Phase 1: template selection (warp k handles template k) ----
    if (t == 20) {
        if (tid < K_TPL) s_sel[tid] = (tid == 0) ? 1 : 0;
        __syncthreads();
    } else {
        if (tid < H_DIM) s_emb[tid] = type_emb[t * H_DIM + tid];
        __syncthreads();

        const int ti = t - 9;
        const float* __restrict__ w  = w_sem + (size_t)ti * ROWS * H_DIM;
        const float* __restrict__ bb = b_sem + (size_t)ti * ROWS;
        const int span = spans[b];

        float best = -CUDART_INF_F;
        int   bestn = 0;
        #pragma unroll 1
        for (int n = 0; n < NP1; n++) {
            const int r = k * NP1 + n;
            const float* __restrict__ wr = w + (size_t)r * H_DIM;
            float acc = wr[lane]      * s_emb[lane]
                      + wr[lane + 32] * s_emb[lane + 32]
                      + wr[lane + 64] * s_emb[lane + 64]
                      + wr[lane + 96] * s_emb[lane + 96];
            #pragma unroll
            for (int o = 16; o; o >>= 1)
                acc += __shfl_xor_sync(0xffffffffu, acc, o);
            if (lane == 0 && n <= span) {
                float val = acc + bb[r] + gumbel[((size_t)b * K_TPL + k) * NP1 + n];
                if (val > best) { best = val; bestn = n; }   // first-max tiebreak
            }
        }
        if (lane == 0) s_sel[k] = bestn;
        __syncthreads();
    }

    // ---- Phase 2: all 8 warps scan their selected rows concurrently ----
    const int sel = s_sel[k];
    int lenmax = 0;
    if (sel > 0) {
        const float4* __restrict__ row4 = (const float4*)
            (decodings + ((size_t)b * N_DEC + (sel - 1)) * (M_LEN * V_VOC));
        const int v4   = lane & 15;     // 16 float4 per position
        const int half = lane >> 4;     // 2 positions per iteration
        #pragma unroll 4
        for (int iter = 0; iter < 64; iter++) {
            const int m = iter * 2 + half;
            float4 x = row4[m * 16 + v4];
            // d[m,0] is x.x of the v4==0 lane of this 16-lane group
            float d0 = __shfl_sync(0xffffffffu, x.x, lane & 16, 32);
            float cm;
            if (v4 == 0) cm = fmaxf(fmaxf(x.y, x.z), x.w);          // exclude v=0
            else         cm = fmaxf(fmaxf(x.x, x.y), fmaxf(x.z, x.w));
            if (cm > d0) lenmax = max(lenmax, m + 1);   // token-0 wins ties
        }
        #pragma unroll
        for (int o = 16; o; o >>= 1)
            lenmax = max(lenmax, __shfl_xor_sync(0xffffffffu, lenmax, o));
    }
    if (lane == 0) s_len[k] = lenmax;
    __syncthreads();

    // ---- offsets: tiny serial scan by thread 0 ----
    if (tid == 0) {
        int cur = 0;
        #pragma unroll
        for (int kk = 0; kk < K_TPL; kk++) {
            const int s   = s_sel[kk];
            const int eff = min(s_len[kk], M_LEN - cur);
            g_src[b * K_TPL + kk] = (s > 0) ? (b * N_DEC + s - 1) : -1;
            g_eff[b * K_TPL + kk] = eff;
            g_off[b * K_TPL + kk] = cur;
            cur += eff;
        }
        g_tot[b] = cur;
    }
}

// ---------------- Kernel 2: fully parallel packed copy + tail zero ----------------
__global__ __launch_bounds__(256, 8)
void pack_copy_kernel(
    const float* __restrict__ decodings,   // [B,16,128,64]
    float*       __restrict__ out)         // [B,128,64]
{
    const int b   = blockIdx.x;
    const int k   = blockIdx.y;            // 0..7 copy, 8 = tail zero
    const int tid = threadIdx.x;

    float* __restrict__ outb = out + (size_t)b * M_LEN * V_VOC;

    if (k == K_TPL) {
        const int tot = g_tot[b];
        float4* __restrict__ o4 = (float4*)outb;
        for (int i = tot * 16 + tid; i < M_LEN * 16; i += 256)
            o4[i] = make_float4(0.f, 0.f, 0.f, 0.f);
        return;
    }

    const int eff = g_eff[b * K_TPL + k];
    if (eff == 0) return;
    const int src = g_src[b * K_TPL + k];
    const int off = g_off[b * K_TPL + k];

    const float4* __restrict__ s4 = (const float4*)
        (decodings + (size_t)src * (M_LEN * V_VOC));
    float4* __restrict__ d4 = (float4*)(outb + off * V_VOC);

    const int n4 = eff * 16;   // float4 count
    #pragma unroll 4
    for (int i = tid; i < n4; i += 256)
        d4[i] = s4[i];
}

extern "C" void kernel_launch(void* const* d_in, const int* in_sizes, int n_in,
                              void* d_out, int out_size)
{
    const float* decodings    = (const float*)d_in[0];
    const float* type_emb     = (const float*)d_in[1];
    const float* w_sem        = (const float*)d_in[2];
    const float* b_sem        = (const float*)d_in[3];
    const float* gumbel       = (const float*)d_in[4];
    const int*   target_types = (const int*)  d_in[5];
    const int*   spans        = (const int*)  d_in[6];
    float*       out          = (float*)d_out;

    const int B = in_sizes[5];

    select_len_kernel<<<B, 256>>>(decodings, type_emb, w_sem, b_sem,
                                  gumbel, target_types, spans);
    dim3 grid2(B, K_TPL + 1);
    pack_copy_kernel<<<grid2, 256>>>(decodings, out);
}